// round 3
// baseline (speedup 1.0000x reference)
#include <cuda_runtime.h>
#include <cstdint>

#define N_NODES_MAX 100000
#define N_EDGES_MAX 1200000
#define DFEAT 64
#define N_GRAPHS 128

// Scratch (device globals: no allocation allowed anywhere)
__device__ __align__(16) float g_agg[N_NODES_MAX * DFEAT];
__device__ __align__(16) float g_h[N_NODES_MAX * DFEAT];
__device__ int g_src[N_EDGES_MAX];
__device__ int g_dst[N_EDGES_MAX];
__device__ int g_gid[N_NODES_MAX];
__device__ int g_idx64;   // 1 if index buffers are int64-laid-out

// ---------------------------------------------------------------------------
// Probe index layout: int64 little-endian => odd int32 words are all zero.
// (indices < 100000 fit in the low word; genuine int32 data has ~0 chance
//  of 32 consecutive odd positions all being exactly 0)
// ---------------------------------------------------------------------------
__global__ void detect_kernel(const int* __restrict__ src, int n) {
    if (threadIdx.x == 0 && blockIdx.x == 0) {
        int allzero = 1;
        int lim = (n > 32) ? 32 : n;
        for (int i = 0; i < lim; i++)
            if (src[2 * i + 1] != 0) allzero = 0;
        g_idx64 = allzero;
    }
}

// Normalize an index array to int32 regardless of source layout.
__global__ void convert_kernel(const void* __restrict__ in, int* __restrict__ out, int n) {
    int i = blockIdx.x * blockDim.x + threadIdx.x;
    int stride = gridDim.x * blockDim.x;
    int f64 = g_idx64;
    for (; i < n; i += stride) {
        out[i] = f64 ? (int)((const long long*)in)[i] : ((const int*)in)[i];
    }
}

// ---------------------------------------------------------------------------
// Zero a float buffer (grid-stride, float4)
// ---------------------------------------------------------------------------
__global__ void zero_kernel(float4* __restrict__ p, int n4) {
    int i = blockIdx.x * blockDim.x + threadIdx.x;
    int stride = gridDim.x * blockDim.x;
    for (; i < n4; i += stride) p[i] = make_float4(0.f, 0.f, 0.f, 0.f);
}

// ---------------------------------------------------------------------------
// Edge scatter: agg[dst] += x[src], 16 threads per edge, float4 + red.v4
// ---------------------------------------------------------------------------
__global__ void scatter_kernel(const float* __restrict__ x,
                               const int* __restrict__ src,
                               const int* __restrict__ dst,
                               float* __restrict__ agg,
                               int n_edges) {
    long long tid = (long long)blockIdx.x * blockDim.x + threadIdx.x;
    int e = (int)(tid >> 4);
    int lane = (int)(tid & 15);
    if (e >= n_edges) return;
    int s = __ldg(&src[e]);
    int d = __ldg(&dst[e]);
    const float4 v = *reinterpret_cast<const float4*>(x + (size_t)s * DFEAT + lane * 4);
    float* p = agg + (size_t)d * DFEAT + lane * 4;
    asm volatile("red.global.add.v4.f32 [%0], {%1,%2,%3,%4};"
                 :: "l"(p), "f"(v.x), "f"(v.y), "f"(v.z), "f"(v.w)
                 : "memory");
}

// ---------------------------------------------------------------------------
// MLP: out[row] = act((x[row]+agg[row]) @ W + b).
// 256 threads, 16 rows per block (4 rows per inner iteration) so the 16KB
// W tile is amortized over 16 rows. W is [in=64,out=64] row-major.
// ---------------------------------------------------------------------------
template <bool RELU>
__global__ void mlp_kernel(const float* __restrict__ x,
                           const float* __restrict__ agg,
                           const float* __restrict__ W,
                           const float* __restrict__ b,
                           float* __restrict__ out,
                           int n_nodes) {
    __shared__ float Ws[DFEAT * DFEAT];
    __shared__ float bs[DFEAT];
    __shared__ float xs[4 * DFEAT];

    int tid = threadIdx.x;
    #pragma unroll
    for (int i = 0; i < 16; i++) Ws[tid + i * 256] = W[tid + i * 256];
    if (tid < DFEAT) bs[tid] = b[tid];

    int r = tid >> 6;        // 0..3
    int col = tid & 63;      // 0..63
    int base = blockIdx.x * 16;

    #pragma unroll
    for (int it = 0; it < 4; it++) {
        int row = base + it * 4 + r;
        bool valid = (row < n_nodes);
        __syncthreads();     // xs safe to overwrite; also covers Ws/bs on it=0
        if (valid) {
            size_t off = (size_t)row * DFEAT + col;
            xs[tid] = x[off] + agg[off];
        }
        __syncthreads();
        if (valid) {
            float sum = bs[col];
            const float* xr = &xs[r * DFEAT];
            #pragma unroll
            for (int k = 0; k < DFEAT; k++)
                sum = fmaf(xr[k], Ws[k * DFEAT + col], sum);
            if (RELU) sum = fmaxf(sum, 0.f);
            out[(size_t)row * DFEAT + col] = sum;
        }
    }
}

// ---------------------------------------------------------------------------
// MLP2 + sum pooling fused. graph_id sorted: carry a (graph, acc) run across
// all 16 rows of the block, one atomic per run boundary per column.
// ---------------------------------------------------------------------------
__global__ void mlp_pool_kernel(const float* __restrict__ x,
                                const float* __restrict__ agg,
                                const float* __restrict__ W,
                                const float* __restrict__ b,
                                const int* __restrict__ gid,
                                float* __restrict__ out,
                                int n_nodes) {
    __shared__ float Ws[DFEAT * DFEAT];
    __shared__ float bs[DFEAT];
    __shared__ float xs[4 * DFEAT];
    __shared__ float vals[4 * DFEAT];
    __shared__ int sgid[16];

    int tid = threadIdx.x;
    #pragma unroll
    for (int i = 0; i < 16; i++) Ws[tid + i * 256] = W[tid + i * 256];
    if (tid < DFEAT) bs[tid] = b[tid];

    int base = blockIdx.x * 16;
    if (tid < 16) {
        int rr = base + tid;
        sgid[tid] = (rr < n_nodes) ? gid[rr] : -1;
    }

    int r = tid >> 6;
    int col = tid & 63;

    int g = -1;          // carried run state (threads tid<64)
    float acc = 0.f;

    #pragma unroll
    for (int it = 0; it < 4; it++) {
        int row = base + it * 4 + r;
        bool valid = (row < n_nodes);
        __syncthreads();     // prev-iter vals readers done; covers smem init on it=0
        if (valid) {
            size_t off = (size_t)row * DFEAT + col;
            xs[tid] = x[off] + agg[off];
        }
        __syncthreads();
        float sum = 0.f;
        if (valid) {
            sum = bs[col];
            const float* xr = &xs[r * DFEAT];
            #pragma unroll
            for (int k = 0; k < DFEAT; k++)
                sum = fmaf(xr[k], Ws[k * DFEAT + col], sum);
        }
        vals[tid] = sum;
        __syncthreads();
        if (tid < DFEAT) {
            #pragma unroll
            for (int rr = 0; rr < 4; rr++) {
                int gr = sgid[it * 4 + rr];
                if (gr < 0) break;
                if (gr != g) {
                    if (g >= 0) atomicAdd(&out[g * DFEAT + tid], acc);
                    g = gr;
                    acc = 0.f;
                }
                acc += vals[rr * DFEAT + tid];
            }
        }
    }
    if (tid < DFEAT && g >= 0) atomicAdd(&out[g * DFEAT + tid], acc);
}

// ---------------------------------------------------------------------------
// Launch
// ---------------------------------------------------------------------------
extern "C" void kernel_launch(void* const* d_in, const int* in_sizes, int n_in,
                              void* d_out, int out_size) {
    const float* feats = (const float*)d_in[0];
    const void* src_raw = d_in[1];
    const void* dst_raw = d_in[2];
    const void* gid_raw = d_in[3];
    const float* W1 = (const float*)d_in[4];
    const float* b1 = (const float*)d_in[5];
    const float* W2 = (const float*)d_in[6];
    const float* b2 = (const float*)d_in[7];
    float* out = (float*)d_out;

    int n_nodes = in_sizes[0] / DFEAT;
    int n_edges = in_sizes[1];

    float* agg; float* h;
    int *src, *dst, *gid;
    cudaGetSymbolAddress((void**)&agg, g_agg);
    cudaGetSymbolAddress((void**)&h, g_h);
    cudaGetSymbolAddress((void**)&src, g_src);
    cudaGetSymbolAddress((void**)&dst, g_dst);
    cudaGetSymbolAddress((void**)&gid, g_gid);

    // 0) probe index layout, normalize indices to int32
    detect_kernel<<<1, 32>>>((const int*)src_raw, n_edges);
    int cgrid = (n_edges + 255) / 256;
    convert_kernel<<<cgrid, 256>>>(src_raw, src, n_edges);
    convert_kernel<<<cgrid, 256>>>(dst_raw, dst, n_edges);
    convert_kernel<<<(n_nodes + 255) / 256, 256>>>(gid_raw, gid, n_nodes);

    int nfeat4 = n_nodes * DFEAT / 4;
    int zgrid = (nfeat4 + 255) / 256;
    int out4 = out_size / 4;

    // 1) zero agg + out
    zero_kernel<<<zgrid, 256>>>((float4*)agg, nfeat4);
    zero_kernel<<<(out4 + 255) / 256, 256>>>((float4*)out, out4);

    // 2) scatter pass 1: agg += feats[src] @ dst
    long long sthreads = (long long)n_edges * 16;
    int sgrid = (int)((sthreads + 255) / 256);
    scatter_kernel<<<sgrid, 256>>>(feats, src, dst, agg, n_edges);

    // 3) h = relu((feats+agg) @ W1 + b1)
    int mgrid = (n_nodes + 15) / 16;
    mlp_kernel<true><<<mgrid, 256>>>(feats, agg, W1, b1, h, n_nodes);

    // 4) re-zero agg
    zero_kernel<<<zgrid, 256>>>((float4*)agg, nfeat4);

    // 5) scatter pass 2: agg += h[src] @ dst
    scatter_kernel<<<sgrid, 256>>>(h, src, dst, agg, n_edges);

    // 6) h2 = (h+agg) @ W2 + b2, fused sum-pool into out
    mlp_pool_kernel<<<mgrid, 256>>>(h, agg, W2, b2, gid, out, n_nodes);
}